// round 1
// baseline (speedup 1.0000x reference)
#include <cuda_runtime.h>
#include <math.h>

#define BB 8
#define SS 2048
#define DD 768

// Scratch for Q, K, V projections (allocation-free: __device__ globals).
__device__ float g_Q[BB * SS * DD];
__device__ float g_K[BB * SS * DD];
__device__ float g_V[BB * SS * DD];

// ----------------------------------------------------------------------------
// Tiled SGEMM: C = alpha * A * op(B)
//   TRANSB=true :  C[m,n] = alpha * sum_k A[m,k] * B[n,k]   (A:MxK, B:NxK)
//   TRANSB=false:  C[m,n] = alpha * sum_k A[m,k] * B[k,n]   (A:MxK, B:KxN)
// Batched via blockIdx.z with element strides sA/sB/sC.
// Tiles: 128x128x16, 256 threads, 8x8 per-thread microtile.
// Requires M%128==0, N%128==0, K%16==0 (true for all shapes here).
// ----------------------------------------------------------------------------
template <bool TRANSB>
__global__ __launch_bounds__(256) void gemm_kernel(
    const float* __restrict__ A, const float* __restrict__ Bm,
    float* __restrict__ C, int M, int N, int K,
    long long sA, long long sB, long long sC, float alpha)
{
    __shared__ float As[16][128];
    __shared__ float Bs[16][128];

    const int tid = threadIdx.x;
    const int tx = tid & 15;   // n direction (8 cols each)
    const int ty = tid >> 4;   // m direction (8 rows each)
    const int m0 = blockIdx.y * 128;
    const int n0 = blockIdx.x * 128;

    A  += (long long)blockIdx.z * sA;
    Bm += (long long)blockIdx.z * sB;
    C  += (long long)blockIdx.z * sC;

    float acc[8][8] = {};

    for (int k0 = 0; k0 < K; k0 += 16) {
        // Load A tile (128 rows x 16 k), transpose into As[k][m]
        #pragma unroll
        for (int i = 0; i < 2; i++) {
            int idx = tid + i * 256;
            int row = idx >> 2;
            int kk  = (idx & 3) * 4;
            float4 v = *(const float4*)(A + (long long)(m0 + row) * K + k0 + kk);
            As[kk + 0][row] = v.x;
            As[kk + 1][row] = v.y;
            As[kk + 2][row] = v.z;
            As[kk + 3][row] = v.w;
        }
        if (TRANSB) {
            // B is NxK row-major: load 128 n-rows x 16 k, transpose into Bs[k][n]
            #pragma unroll
            for (int i = 0; i < 2; i++) {
                int idx = tid + i * 256;
                int row = idx >> 2;
                int kk  = (idx & 3) * 4;
                float4 v = *(const float4*)(Bm + (long long)(n0 + row) * K + k0 + kk);
                Bs[kk + 0][row] = v.x;
                Bs[kk + 1][row] = v.y;
                Bs[kk + 2][row] = v.z;
                Bs[kk + 3][row] = v.w;
            }
        } else {
            // B is KxN row-major: load 16 k-rows x 128 n directly into Bs[k][n]
            #pragma unroll
            for (int i = 0; i < 2; i++) {
                int idx = tid + i * 256;
                int kk  = idx >> 5;
                int n4  = (idx & 31) * 4;
                *(float4*)&Bs[kk][n4] =
                    *(const float4*)(Bm + (long long)(k0 + kk) * N + n0 + n4);
            }
        }
        __syncthreads();

        #pragma unroll
        for (int kk = 0; kk < 16; kk++) {
            float a[8], b[8];
            *(float4*)(a)     = *(const float4*)&As[kk][ty * 8];
            *(float4*)(a + 4) = *(const float4*)&As[kk][ty * 8 + 4];
            *(float4*)(b)     = *(const float4*)&Bs[kk][tx * 8];
            *(float4*)(b + 4) = *(const float4*)&Bs[kk][tx * 8 + 4];
            #pragma unroll
            for (int i = 0; i < 8; i++)
                #pragma unroll
                for (int j = 0; j < 8; j++)
                    acc[i][j] = fmaf(a[i], b[j], acc[i][j]);
        }
        __syncthreads();
    }

    #pragma unroll
    for (int i = 0; i < 8; i++) {
        float* cp = C + (long long)(m0 + ty * 8 + i) * N + n0 + tx * 8;
        float4 v0, v1;
        v0.x = acc[i][0] * alpha; v0.y = acc[i][1] * alpha;
        v0.z = acc[i][2] * alpha; v0.w = acc[i][3] * alpha;
        v1.x = acc[i][4] * alpha; v1.y = acc[i][5] * alpha;
        v1.z = acc[i][6] * alpha; v1.w = acc[i][7] * alpha;
        *(float4*)(cp)     = v0;
        *(float4*)(cp + 4) = v1;
    }
}

// ----------------------------------------------------------------------------
// Row softmax in place over rows of length SS=2048. One block (256 thr) per row.
// ----------------------------------------------------------------------------
__global__ __launch_bounds__(256) void softmax_kernel(float* __restrict__ attn)
{
    __shared__ float red[256];
    const long long row = blockIdx.x;
    float* p = attn + row * (long long)SS;
    const int tid = threadIdx.x;

    float v[8];
    float mx = -1e30f;
    #pragma unroll
    for (int i = 0; i < 8; i++) {
        v[i] = p[tid + i * 256];
        mx = fmaxf(mx, v[i]);
    }
    red[tid] = mx;
    __syncthreads();
    for (int s = 128; s > 0; s >>= 1) {
        if (tid < s) red[tid] = fmaxf(red[tid], red[tid + s]);
        __syncthreads();
    }
    mx = red[0];
    __syncthreads();

    float sum = 0.0f;
    #pragma unroll
    for (int i = 0; i < 8; i++) {
        v[i] = __expf(v[i] - mx);
        sum += v[i];
    }
    red[tid] = sum;
    __syncthreads();
    for (int s = 128; s > 0; s >>= 1) {
        if (tid < s) red[tid] += red[tid + s];
        __syncthreads();
    }
    const float inv = 1.0f / red[0];

    #pragma unroll
    for (int i = 0; i < 8; i++)
        p[tid + i * 256] = v[i] * inv;
}

extern "C" void kernel_launch(void* const* d_in, const int* in_sizes, int n_in,
                              void* d_out, int out_size)
{
    const float* x  = (const float*)d_in[0];
    const float* Wq = (const float*)d_in[1];
    const float* Wk = (const float*)d_in[2];
    const float* Wv = (const float*)d_in[3];

    float* out  = (float*)d_out;                       // weighted_values [B,S,D]
    float* attn = out + (long long)BB * SS * DD;       // attention_weights [B,S,S]

    float *Q, *K, *V;
    cudaGetSymbolAddress((void**)&Q, g_Q);
    cudaGetSymbolAddress((void**)&K, g_K);
    cudaGetSymbolAddress((void**)&V, g_V);

    dim3 blk(256);

    // QKV projections: [16384 x 768] = x[16384 x 768] * W^T (W is [768,768] row-major [out,in])
    dim3 gq(DD / 128, (BB * SS) / 128, 1);
    gemm_kernel<true><<<gq, blk>>>(x, Wq, Q, BB * SS, DD, DD, 0, 0, 0, 1.0f);
    gemm_kernel<true><<<gq, blk>>>(x, Wk, K, BB * SS, DD, DD, 0, 0, 0, 1.0f);
    gemm_kernel<true><<<gq, blk>>>(x, Wv, V, BB * SS, DD, DD, 0, 0, 0, 1.0f);

    // Scores: per batch, S x S = Q * K^T, scaled by 1/sqrt(D)
    dim3 gs(SS / 128, SS / 128, BB);
    const float alpha = 1.0f / sqrtf((float)DD);
    gemm_kernel<true><<<gs, blk>>>(Q, K, attn, SS, SS, DD,
                                   (long long)SS * DD, (long long)SS * DD,
                                   (long long)SS * SS, alpha);

    // Softmax rows (in place -> final attention_weights output)
    softmax_kernel<<<BB * SS, blk>>>(attn);

    // Weighted values: per batch, S x D = attn[S x S] * V[S x D]
    dim3 ga(DD / 128, SS / 128, BB);
    gemm_kernel<false><<<ga, blk>>>(attn, V, out, SS, DD, SS,
                                    (long long)SS * SS, (long long)SS * DD,
                                    (long long)SS * DD, 1.0f);
}

// round 2
// speedup vs baseline: 2.9255x; 2.9255x over previous
#include <cuda_runtime.h>
#include <math.h>
#include <stdint.h>

#define BB 8
#define SS 2048
#define DD 768

// Scratch (allocation-free: __device__ globals).
__device__ float g_Q [BB * SS * DD];
__device__ float g_K [BB * SS * DD];
__device__ float g_VT[BB * DD * SS];   // V transposed per batch: [B][D][S]

__device__ __forceinline__ uint32_t f2tf32(float f) {
    uint32_t r;
    asm("cvt.rna.tf32.f32 %0, %1;" : "=r"(r) : "f"(f));
    return r;
}

__device__ __forceinline__ void ldsm4(uint32_t& r0, uint32_t& r1,
                                      uint32_t& r2, uint32_t& r3, uint32_t addr) {
    asm volatile("ldmatrix.sync.aligned.m8n8.x4.shared.b16 {%0,%1,%2,%3}, [%4];"
                 : "=r"(r0), "=r"(r1), "=r"(r2), "=r"(r3) : "r"(addr));
}

__device__ __forceinline__ void mma8(float* c, const uint32_t* a,
                                     uint32_t b0, uint32_t b1) {
    asm volatile(
        "mma.sync.aligned.m16n8k8.row.col.f32.tf32.tf32.f32 "
        "{%0,%1,%2,%3}, {%4,%5,%6,%7}, {%8,%9}, {%0,%1,%2,%3};"
        : "+f"(c[0]), "+f"(c[1]), "+f"(c[2]), "+f"(c[3])
        : "r"(a[0]), "r"(a[1]), "r"(a[2]), "r"(a[3]), "r"(b0), "r"(b1));
}

// ----------------------------------------------------------------------------
// TN tf32 tensor-core GEMM:  C[m,n] = alpha * sum_k A[m,k] * B[n,k]
// A: MxK row-major, B: NxK row-major. Batched via blockIdx.z (strides sA/sB/sC).
// Block tile 128x128x16, 8 warps (4m x 2n), warp tile 32x64 of m16n8k8 MMAs.
// Requires M%128==0, N%128==0, K%16==0.
// Smem tiles stored k-major with SW128 swizzle (byte ^ ((byte>>3)&0x70)).
// ----------------------------------------------------------------------------
__global__ __launch_bounds__(256, 2) void gemm_tn_tf32(
    const float* __restrict__ A, const float* __restrict__ B,
    float* __restrict__ C, int M, int N, int K,
    long long sA, long long sB, long long sC, float alpha)
{
    __shared__ __align__(128) uint32_t As[128 * 16];
    __shared__ __align__(128) uint32_t Bs[128 * 16];

    const int tid  = threadIdx.x;
    const int lane = tid & 31;
    const int warp = tid >> 5;
    const int wm   = warp >> 1;    // 0..3 (m direction, 32 rows each)
    const int wn   = warp & 1;     // 0..1 (n direction, 64 cols each)
    const int m0   = blockIdx.y * 128;
    const int n0   = blockIdx.x * 128;

    A += (long long)blockIdx.z * sA;
    B += (long long)blockIdx.z * sB;
    C += (long long)blockIdx.z * sC;

    const uint32_t as_base = (uint32_t)__cvta_generic_to_shared(As);
    const uint32_t bs_base = (uint32_t)__cvta_generic_to_shared(Bs);

    float acc[2][8][4] = {};

    for (int k0 = 0; k0 < K; k0 += 16) {
        // Fill As: 128 rows x 16 k (tf32), swizzled. 512 16B-chunks, 2 per thread.
        #pragma unroll
        for (int i = 0; i < 2; i++) {
            int cid = tid + i * 256;
            int row = cid >> 2, g = cid & 3;
            float4 v = *(const float4*)(A + (long long)(m0 + row) * K + k0 + g * 4);
            uint32_t byte = (uint32_t)(row * 64 + g * 16);
            uint32_t off  = (byte ^ ((byte >> 3) & 0x70)) >> 2;
            As[off + 0] = f2tf32(v.x); As[off + 1] = f2tf32(v.y);
            As[off + 2] = f2tf32(v.z); As[off + 3] = f2tf32(v.w);
        }
        // Fill Bs: identical pattern (B is NxK row-major).
        #pragma unroll
        for (int i = 0; i < 2; i++) {
            int cid = tid + i * 256;
            int row = cid >> 2, g = cid & 3;
            float4 v = *(const float4*)(B + (long long)(n0 + row) * K + k0 + g * 4);
            uint32_t byte = (uint32_t)(row * 64 + g * 16);
            uint32_t off  = (byte ^ ((byte >> 3) & 0x70)) >> 2;
            Bs[off + 0] = f2tf32(v.x); Bs[off + 1] = f2tf32(v.y);
            Bs[off + 2] = f2tf32(v.z); Bs[off + 3] = f2tf32(v.w);
        }
        __syncthreads();

        #pragma unroll
        for (int ks = 0; ks < 2; ks++) {
            uint32_t a[2][4], b[4][4];
            // A fragments: 2 x (m16 x k8) per warp via ldmatrix.x4
            #pragma unroll
            for (int mi = 0; mi < 2; mi++) {
                int row = wm * 32 + mi * 16 + (lane & 7) + ((lane >> 3) & 1) * 8;
                int g   = ks * 2 + (lane >> 4);
                uint32_t byte = (uint32_t)(row * 64 + g * 16);
                ldsm4(a[mi][0], a[mi][1], a[mi][2], a[mi][3],
                      as_base + (byte ^ ((byte >> 3) & 0x70)));
            }
            // B fragments: 8 x (n8 x k8) per warp, pairs via ldmatrix.x4
            #pragma unroll
            for (int bi = 0; bi < 4; bi++) {
                int row = wn * 64 + bi * 16 + (lane & 7) + ((lane >> 3) & 1) * 8;
                int g   = ks * 2 + (lane >> 4);
                uint32_t byte = (uint32_t)(row * 64 + g * 16);
                ldsm4(b[bi][0], b[bi][1], b[bi][2], b[bi][3],
                      bs_base + (byte ^ ((byte >> 3) & 0x70)));
            }
            #pragma unroll
            for (int mi = 0; mi < 2; mi++)
                #pragma unroll
                for (int bi = 0; bi < 4; bi++) {
                    mma8(acc[mi][2 * bi + 0], a[mi], b[bi][0], b[bi][2]);
                    mma8(acc[mi][2 * bi + 1], a[mi], b[bi][1], b[bi][3]);
                }
        }
        __syncthreads();
    }

    // Epilogue
    const int r0 = m0 + wm * 32 + (lane >> 2);
    const int c0 = n0 + wn * 64 + (lane & 3) * 2;
    #pragma unroll
    for (int mi = 0; mi < 2; mi++)
        #pragma unroll
        for (int ni = 0; ni < 8; ni++) {
            float* p = C + (long long)(r0 + mi * 16) * N + c0 + ni * 8;
            float2 v0, v1;
            v0.x = acc[mi][ni][0] * alpha; v0.y = acc[mi][ni][1] * alpha;
            v1.x = acc[mi][ni][2] * alpha; v1.y = acc[mi][ni][3] * alpha;
            *(float2*)p = v0;
            *(float2*)(p + 8LL * N) = v1;
        }
}

// ----------------------------------------------------------------------------
// Row softmax in place over rows of length SS=2048. One block (256 thr) per row.
// ----------------------------------------------------------------------------
__global__ __launch_bounds__(256) void softmax_kernel(float* __restrict__ attn)
{
    __shared__ float red[256];
    const long long row = blockIdx.x;
    float* p = attn + row * (long long)SS;
    const int tid = threadIdx.x;

    float v[8];
    float mx = -1e30f;
    #pragma unroll
    for (int i = 0; i < 8; i++) {
        v[i] = p[tid + i * 256];
        mx = fmaxf(mx, v[i]);
    }
    red[tid] = mx;
    __syncthreads();
    for (int s = 128; s > 0; s >>= 1) {
        if (tid < s) red[tid] = fmaxf(red[tid], red[tid + s]);
        __syncthreads();
    }
    mx = red[0];
    __syncthreads();

    float sum = 0.0f;
    #pragma unroll
    for (int i = 0; i < 8; i++) {
        v[i] = __expf(v[i] - mx);
        sum += v[i];
    }
    red[tid] = sum;
    __syncthreads();
    for (int s = 128; s > 0; s >>= 1) {
        if (tid < s) red[tid] += red[tid + s];
        __syncthreads();
    }
    const float inv = 1.0f / red[0];

    #pragma unroll
    for (int i = 0; i < 8; i++)
        p[tid + i * 256] = v[i] * inv;
}

extern "C" void kernel_launch(void* const* d_in, const int* in_sizes, int n_in,
                              void* d_out, int out_size)
{
    const float* x  = (const float*)d_in[0];
    const float* Wq = (const float*)d_in[1];
    const float* Wk = (const float*)d_in[2];
    const float* Wv = (const float*)d_in[3];

    float* out  = (float*)d_out;                   // weighted_values [B,S,D]
    float* attn = out + (long long)BB * SS * DD;   // attention_weights [B,S,S]

    float *Q, *K, *VT;
    cudaGetSymbolAddress((void**)&Q,  g_Q);
    cudaGetSymbolAddress((void**)&K,  g_K);
    cudaGetSymbolAddress((void**)&VT, g_VT);

    dim3 blk(256);
    const float alpha = 1.0f / sqrtf((float)DD);

    // Q = x @ Wq^T, K = x @ Wk^T   (TN: A=x [16384x768], B=W [768x768])
    dim3 gq(DD / 128, (BB * SS) / 128, 1);
    gemm_tn_tf32<<<gq, blk>>>(x, Wq, Q, BB * SS, DD, DD, 0, 0, 0, 1.0f);
    gemm_tn_tf32<<<gq, blk>>>(x, Wk, K, BB * SS, DD, DD, 0, 0, 0, 1.0f);

    // V^T directly: VT_b[d][s] = sum_k Wv[d][k] * x_b[s][k]
    // (TN: A=Wv [768x768], B=x_b [2048x768], batched over b)
    dim3 gv(SS / 128, DD / 128, BB);
    gemm_tn_tf32<<<gv, blk>>>(Wv, x, VT, DD, SS, DD,
                              0, (long long)SS * DD, (long long)DD * SS, 1.0f);

    // Scores: attn_b = (Q_b @ K_b^T) * alpha   (TN: A=Q_b, B=K_b)
    dim3 gs(SS / 128, SS / 128, BB);
    gemm_tn_tf32<<<gs, blk>>>(Q, K, attn, SS, SS, DD,
                              (long long)SS * DD, (long long)SS * DD,
                              (long long)SS * SS, alpha);

    // Softmax rows (in place -> final attention_weights output)
    softmax_kernel<<<BB * SS, blk>>>(attn);

    // Weighted values: out_b[s][d] = sum_k attn_b[s][k] * VT_b[d][k]  (TN: B=VT_b)
    dim3 ga(DD / 128, SS / 128, BB);
    gemm_tn_tf32<<<ga, blk>>>(attn, VT, out, SS, DD, SS,
                              (long long)SS * SS, (long long)DD * SS,
                              (long long)SS * DD, 1.0f);
}

// round 3
// speedup vs baseline: 3.1518x; 1.0773x over previous
#include <cuda_runtime.h>
#include <math.h>
#include <stdint.h>

#define BB 8
#define SS 2048
#define DD 768

// Scratch (allocation-free: __device__ globals).
__device__ float g_Q [BB * SS * DD];
__device__ float g_K [BB * SS * DD];
__device__ float g_VT[BB * DD * SS];   // V transposed per batch: [B][D][S]

__device__ __forceinline__ uint32_t f2tf32(float f) {
    uint32_t r;
    asm("cvt.rna.tf32.f32 %0, %1;" : "=r"(r) : "f"(f));
    return r;
}
__device__ __forceinline__ uint32_t swz(uint32_t byte) {
    return byte ^ ((byte >> 3) & 0x70);
}
__device__ __forceinline__ void ldsm4(uint32_t& r0, uint32_t& r1,
                                      uint32_t& r2, uint32_t& r3, uint32_t addr) {
    asm volatile("ldmatrix.sync.aligned.m8n8.x4.shared.b16 {%0,%1,%2,%3}, [%4];"
                 : "=r"(r0), "=r"(r1), "=r"(r2), "=r"(r3) : "r"(addr));
}
__device__ __forceinline__ void mma8(float* c, const uint32_t* a,
                                     uint32_t b0, uint32_t b1) {
    asm volatile(
        "mma.sync.aligned.m16n8k8.row.col.f32.tf32.tf32.f32 "
        "{%0,%1,%2,%3}, {%4,%5,%6,%7}, {%8,%9}, {%0,%1,%2,%3};"
        : "+f"(c[0]), "+f"(c[1]), "+f"(c[2]), "+f"(c[3])
        : "r"(a[0]), "r"(a[1]), "r"(a[2]), "r"(a[3]), "r"(b0), "r"(b1));
}
__device__ __forceinline__ void cp16(uint32_t dst, const float* src) {
    asm volatile("cp.async.cg.shared.global [%0], [%1], 16;"
                 :: "r"(dst), "l"(src));
}
__device__ __forceinline__ void cp_commit() {
    asm volatile("cp.async.commit_group;" ::: "memory");
}
__device__ __forceinline__ void cp_wait1() {
    asm volatile("cp.async.wait_group 1;" ::: "memory");
}

// ----------------------------------------------------------------------------
// TN tf32 tensor-core GEMM:  C[m,n] = alpha * sum_k A[m,k] * B[n,k]
// A: MxK row-major, B: NxK row-major. Batched via blockIdx.z (strides sA/sB/sC).
// Block tile 128x128x16, 3-stage cp.async pipeline, 8 warps (4m x 2n),
// warp tile 32x64 of m16n8k8 tf32 MMAs. fp32 lands raw in SW128-swizzled smem;
// RNA tf32 conversion applied on fragments after ldmatrix.
// Requires M%128==0, N%128==0, K%32==0 (all shapes here comply).
// ----------------------------------------------------------------------------
#define STAGE_BYTES 16384    // 8KB A + 8KB B
__global__ __launch_bounds__(256, 2) void gemm_tn_tf32(
    const float* __restrict__ A, const float* __restrict__ B,
    float* __restrict__ C, int M, int N, int K,
    long long sA, long long sB, long long sC, float alpha)
{
    __shared__ __align__(1024) uint8_t sm[3 * STAGE_BYTES];

    const int tid  = threadIdx.x;
    const int lane = tid & 31;
    const int warp = tid >> 5;
    const int wm   = warp >> 1;    // 0..3 (m direction, 32 rows each)
    const int wn   = warp & 1;     // 0..1 (n direction, 64 cols each)
    const int m0   = blockIdx.y * 128;
    const int n0   = blockIdx.x * 128;

    A += (long long)blockIdx.z * sA;
    B += (long long)blockIdx.z * sB;
    C += (long long)blockIdx.z * sC;

    const uint32_t smbase = (uint32_t)__cvta_generic_to_shared(sm);

    // Per-thread fill coordinates: 512 16B chunks per tile, 2 per thread.
    const int cr = tid >> 2;          // row 0..63 (chunk 0), +64 (chunk 1)
    const int cg = tid & 3;           // 16B group within 64B row
    const uint32_t oA0 = swz((uint32_t)(cr * 64 + cg * 16));
    const uint32_t oA1 = swz((uint32_t)((cr + 64) * 64 + cg * 16));

    const float* a0 = A + (long long)(m0 + cr) * K + cg * 4;
    const float* a1 = A + (long long)(m0 + cr + 64) * K + cg * 4;
    const float* b0 = B + (long long)(n0 + cr) * K + cg * 4;
    const float* b1 = B + (long long)(n0 + cr + 64) * K + cg * 4;

    const int KT = K >> 4;   // k-tiles of 16

    #define ISSUE_TILE(t) do {                                   \
        uint32_t sb = smbase + ((t) % 3) * STAGE_BYTES;          \
        int ko = (t) << 4;                                       \
        cp16(sb + oA0,        a0 + ko);                          \
        cp16(sb + oA1,        a1 + ko);                          \
        cp16(sb + 8192 + oA0, b0 + ko);                          \
        cp16(sb + 8192 + oA1, b1 + ko);                          \
    } while (0)

    ISSUE_TILE(0); cp_commit();
    ISSUE_TILE(1); cp_commit();

    float acc[2][8][4] = {};

    // Hoisted ldsm row/group components (swizzle applied per step).
    const int lrow = (lane & 7) + ((lane >> 3) & 1) * 8;
    const int lgrp = lane >> 4;

    for (int i = 0; i < KT; i++) {
        cp_wait1();
        __syncthreads();
        if (i + 2 < KT) ISSUE_TILE(i + 2);
        cp_commit();

        const uint32_t stage = smbase + (i % 3) * STAGE_BYTES;

        #pragma unroll
        for (int ks = 0; ks < 2; ks++) {
            uint32_t a[2][4], b[4][4];
            const int g = ks * 2 + lgrp;
            #pragma unroll
            for (int mi = 0; mi < 2; mi++) {
                int row = wm * 32 + mi * 16 + lrow;
                ldsm4(a[mi][0], a[mi][1], a[mi][2], a[mi][3],
                      stage + swz((uint32_t)(row * 64 + g * 16)));
            }
            #pragma unroll
            for (int bi = 0; bi < 4; bi++) {
                int row = wn * 64 + bi * 16 + lrow;
                ldsm4(b[bi][0], b[bi][1], b[bi][2], b[bi][3],
                      stage + 8192 + swz((uint32_t)(row * 64 + g * 16)));
            }
            // RNA tf32 rounding on fragments (matches cvt.rna path numerics).
            #pragma unroll
            for (int mi = 0; mi < 2; mi++)
                #pragma unroll
                for (int r = 0; r < 4; r++)
                    a[mi][r] = f2tf32(__uint_as_float(a[mi][r]));
            #pragma unroll
            for (int bi = 0; bi < 4; bi++)
                #pragma unroll
                for (int r = 0; r < 4; r++)
                    b[bi][r] = f2tf32(__uint_as_float(b[bi][r]));

            #pragma unroll
            for (int mi = 0; mi < 2; mi++)
                #pragma unroll
                for (int bi = 0; bi < 4; bi++) {
                    mma8(acc[mi][2 * bi + 0], a[mi], b[bi][0], b[bi][2]);
                    mma8(acc[mi][2 * bi + 1], a[mi], b[bi][1], b[bi][3]);
                }
        }
    }

    // Epilogue
    const int r0 = m0 + wm * 32 + (lane >> 2);
    const int c0 = n0 + wn * 64 + (lane & 3) * 2;
    #pragma unroll
    for (int mi = 0; mi < 2; mi++)
        #pragma unroll
        for (int ni = 0; ni < 8; ni++) {
            float* p = C + (long long)(r0 + mi * 16) * N + c0 + ni * 8;
            float2 v0, v1;
            v0.x = acc[mi][ni][0] * alpha; v0.y = acc[mi][ni][1] * alpha;
            v1.x = acc[mi][ni][2] * alpha; v1.y = acc[mi][ni][3] * alpha;
            *(float2*)p = v0;
            *(float2*)(p + 8LL * N) = v1;
        }
    #undef ISSUE_TILE
}

// ----------------------------------------------------------------------------
// Row softmax in place over rows of length SS=2048. One block (256 thr) per row.
// ----------------------------------------------------------------------------
__global__ __launch_bounds__(256) void softmax_kernel(float* __restrict__ attn)
{
    __shared__ float red[256];
    const long long row = blockIdx.x;
    float* p = attn + row * (long long)SS;
    const int tid = threadIdx.x;

    float v[8];
    float mx = -1e30f;
    #pragma unroll
    for (int i = 0; i < 8; i++) {
        v[i] = p[tid + i * 256];
        mx = fmaxf(mx, v[i]);
    }
    red[tid] = mx;
    __syncthreads();
    for (int s = 128; s > 0; s >>= 1) {
        if (tid < s) red[tid] = fmaxf(red[tid], red[tid + s]);
        __syncthreads();
    }
    mx = red[0];
    __syncthreads();

    float sum = 0.0f;
    #pragma unroll
    for (int i = 0; i < 8; i++) {
        v[i] = __expf(v[i] - mx);
        sum += v[i];
    }
    red[tid] = sum;
    __syncthreads();
    for (int s = 128; s > 0; s >>= 1) {
        if (tid < s) red[tid] += red[tid + s];
        __syncthreads();
    }
    const float inv = 1.0f / red[0];

    #pragma unroll
    for (int i = 0; i < 8; i++)
        p[tid + i * 256] = v[i] * inv;
}

extern "C" void kernel_launch(void* const* d_in, const int* in_sizes, int n_in,
                              void* d_out, int out_size)
{
    const float* x  = (const float*)d_in[0];
    const float* Wq = (const float*)d_in[1];
    const float* Wk = (const float*)d_in[2];
    const float* Wv = (const float*)d_in[3];

    float* out  = (float*)d_out;                   // weighted_values [B,S,D]
    float* attn = out + (long long)BB * SS * DD;   // attention_weights [B,S,S]

    float *Q, *K, *VT;
    cudaGetSymbolAddress((void**)&Q,  g_Q);
    cudaGetSymbolAddress((void**)&K,  g_K);
    cudaGetSymbolAddress((void**)&VT, g_VT);

    dim3 blk(256);
    const float alpha = 1.0f / sqrtf((float)DD);

    // Q = x @ Wq^T, K = x @ Wk^T   (TN: A=x [16384x768], B=W [768x768])
    dim3 gq(DD / 128, (BB * SS) / 128, 1);
    gemm_tn_tf32<<<gq, blk>>>(x, Wq, Q, BB * SS, DD, DD, 0, 0, 0, 1.0f);
    gemm_tn_tf32<<<gq, blk>>>(x, Wk, K, BB * SS, DD, DD, 0, 0, 0, 1.0f);

    // V^T directly: VT_b[d][s] = sum_k Wv[d][k] * x_b[s][k]
    dim3 gv(SS / 128, DD / 128, BB);
    gemm_tn_tf32<<<gv, blk>>>(Wv, x, VT, DD, SS, DD,
                              0, (long long)SS * DD, (long long)DD * SS, 1.0f);

    // Scores: attn_b = (Q_b @ K_b^T) * alpha   (TN: A=Q_b, B=K_b)
    dim3 gs(SS / 128, SS / 128, BB);
    gemm_tn_tf32<<<gs, blk>>>(Q, K, attn, SS, SS, DD,
                              (long long)SS * DD, (long long)SS * DD,
                              (long long)SS * SS, alpha);

    // Softmax rows (in place -> final attention_weights output)
    softmax_kernel<<<BB * SS, blk>>>(attn);

    // Weighted values: out_b[s][d] = sum_k attn_b[s][k] * VT_b[d][k]  (TN: B=VT_b)
    dim3 ga(DD / 128, SS / 128, BB);
    gemm_tn_tf32<<<ga, blk>>>(attn, VT, out, SS, DD, SS,
                              (long long)SS * SS, (long long)DD * SS,
                              (long long)SS * DD, 1.0f);
}

// round 4
// speedup vs baseline: 3.8416x; 1.2189x over previous
#include <cuda_runtime.h>
#include <math.h>
#include <stdint.h>

#define BB 8
#define SS 2048
#define DD 768

// Scratch (allocation-free: __device__ globals). All values tf32-rounded fp32.
__device__ float g_Q [BB * SS * DD];
__device__ float g_K [BB * SS * DD];
__device__ float g_VT[BB * DD * SS];      // V transposed per batch: [B][D][S]
__device__ float g_Xt[BB * SS * DD];      // x pre-rounded to tf32
__device__ float g_Wt[3 * DD * DD];       // Wq|Wk|Wv pre-rounded to tf32
__device__ float g_At[BB * SS * SS];      // softmax output rounded to tf32

__device__ __forceinline__ uint32_t f2tf32(float f) {
    uint32_t r;
    asm("cvt.rna.tf32.f32 %0, %1;" : "=r"(r) : "f"(f));
    return r;
}
__device__ __forceinline__ float f2tf32f(float f) {
    return __uint_as_float(f2tf32(f));
}
__device__ __forceinline__ uint32_t swz(uint32_t byte) {
    return byte ^ ((byte >> 3) & 0x70);
}
__device__ __forceinline__ void ldsm4(uint32_t& r0, uint32_t& r1,
                                      uint32_t& r2, uint32_t& r3, uint32_t addr) {
    asm volatile("ldmatrix.sync.aligned.m8n8.x4.shared.b16 {%0,%1,%2,%3}, [%4];"
                 : "=r"(r0), "=r"(r1), "=r"(r2), "=r"(r3) : "r"(addr));
}
__device__ __forceinline__ void mma8(float* c, const uint32_t* a,
                                     uint32_t b0, uint32_t b1) {
    asm volatile(
        "mma.sync.aligned.m16n8k8.row.col.f32.tf32.tf32.f32 "
        "{%0,%1,%2,%3}, {%4,%5,%6,%7}, {%8,%9}, {%0,%1,%2,%3};"
        : "+f"(c[0]), "+f"(c[1]), "+f"(c[2]), "+f"(c[3])
        : "r"(a[0]), "r"(a[1]), "r"(a[2]), "r"(a[3]), "r"(b0), "r"(b1));
}
__device__ __forceinline__ void cp16(uint32_t dst, const float* src) {
    asm volatile("cp.async.cg.shared.global [%0], [%1], 16;"
                 :: "r"(dst), "l"(src));
}
__device__ __forceinline__ void cp_commit() {
    asm volatile("cp.async.commit_group;" ::: "memory");
}
__device__ __forceinline__ void cp_wait1() {
    asm volatile("cp.async.wait_group 1;" ::: "memory");
}

// ----------------------------------------------------------------------------
// Elementwise tf32 rounding: out[i] = tf32(in[i]), vectorized float4.
// ----------------------------------------------------------------------------
__global__ __launch_bounds__(256) void cvt_tf32_kernel(
    const float4* __restrict__ in, float4* __restrict__ out, int n4)
{
    int i = blockIdx.x * 256 + threadIdx.x;
    if (i < n4) {
        float4 v = in[i];
        v.x = f2tf32f(v.x); v.y = f2tf32f(v.y);
        v.z = f2tf32f(v.z); v.w = f2tf32f(v.w);
        out[i] = v;
    }
}

// ----------------------------------------------------------------------------
// TN tf32 tensor-core GEMM:  C[m,n] = alpha * sum_k A[m,k] * B[n,k]
// A: MxK row-major, B: NxK row-major (both already tf32-valued fp32).
// Batched via blockIdx.z (strides sA/sB/sC). Block tile 128x128x16, 3-stage
// cp.async pipeline, 8 warps (4m x 2n), warp tile 32x64 of m16n8k8 tf32 MMAs.
// No cvt in mainloop; ldsm addresses hoisted (swz(rowbyte+g*16)=swz(rowbyte)^(g*16)).
// EPI_TF32: round outputs to tf32 (for intermediates consumed by later GEMMs).
// Requires M%128==0, N%128==0, K%16==0.
// ----------------------------------------------------------------------------
#define STAGE_BYTES 16384    // 8KB A + 8KB B
template <bool EPI_TF32>
__global__ __launch_bounds__(256, 2) void gemm_tn_tf32(
    const float* __restrict__ A, const float* __restrict__ B,
    float* __restrict__ C, int M, int N, int K,
    long long sA, long long sB, long long sC, float alpha)
{
    __shared__ __align__(1024) uint8_t sm[3 * STAGE_BYTES];

    const int tid  = threadIdx.x;
    const int lane = tid & 31;
    const int warp = tid >> 5;
    const int wm   = warp >> 1;    // 0..3 (m direction, 32 rows each)
    const int wn   = warp & 1;     // 0..1 (n direction, 64 cols each)
    const int m0   = blockIdx.y * 128;
    const int n0   = blockIdx.x * 128;

    A += (long long)blockIdx.z * sA;
    B += (long long)blockIdx.z * sB;
    C += (long long)blockIdx.z * sC;

    const uint32_t smbase = (uint32_t)__cvta_generic_to_shared(sm);

    // Per-thread fill coordinates: 512 16B chunks per tile, 2 per thread.
    const int cr = tid >> 2;
    const int cg = tid & 3;
    const uint32_t oA0 = swz((uint32_t)(cr * 64 + cg * 16));
    const uint32_t oA1 = swz((uint32_t)((cr + 64) * 64 + cg * 16));

    const float* a0 = A + (long long)(m0 + cr) * K + cg * 4;
    const float* a1 = A + (long long)(m0 + cr + 64) * K + cg * 4;
    const float* b0 = B + (long long)(n0 + cr) * K + cg * 4;
    const float* b1 = B + (long long)(n0 + cr + 64) * K + cg * 4;

    const int KT = K >> 4;

    #define ISSUE_TILE(t) do {                                   \
        uint32_t sb = smbase + ((t) % 3) * STAGE_BYTES;          \
        int ko = (t) << 4;                                       \
        cp16(sb + oA0,        a0 + ko);                          \
        cp16(sb + oA1,        a1 + ko);                          \
        cp16(sb + 8192 + oA0, b0 + ko);                          \
        cp16(sb + 8192 + oA1, b1 + ko);                          \
    } while (0)

    ISSUE_TILE(0); cp_commit();
    ISSUE_TILE(1); cp_commit();

    float acc[2][8][4] = {};

    // Hoisted swizzled ldsm base offsets (per-thread constants).
    const int lrow = (lane & 7) + ((lane >> 3) & 1) * 8;
    const uint32_t glo = (uint32_t)(lane >> 4) * 16;   // 0 or 16
    uint32_t aoff[2], boff[4];
    #pragma unroll
    for (int mi = 0; mi < 2; mi++)
        aoff[mi] = swz((uint32_t)((wm * 32 + mi * 16 + lrow) * 64)) ^ glo;
    #pragma unroll
    for (int bi = 0; bi < 4; bi++)
        boff[bi] = (swz((uint32_t)((wn * 64 + bi * 16 + lrow) * 64)) ^ glo) + 8192;

    for (int i = 0; i < KT; i++) {
        cp_wait1();
        __syncthreads();
        if (i + 2 < KT) ISSUE_TILE(i + 2);
        cp_commit();

        const uint32_t stage = smbase + (i % 3) * STAGE_BYTES;

        #pragma unroll
        for (int ks = 0; ks < 2; ks++) {
            const uint32_t gx = (uint32_t)(ks * 32);  // g*16 = ks*32 ^ glo (disjoint bits)
            uint32_t a[2][4], b[4][4];
            #pragma unroll
            for (int mi = 0; mi < 2; mi++)
                ldsm4(a[mi][0], a[mi][1], a[mi][2], a[mi][3],
                      stage + (aoff[mi] ^ gx));
            #pragma unroll
            for (int bi = 0; bi < 4; bi++)
                ldsm4(b[bi][0], b[bi][1], b[bi][2], b[bi][3],
                      stage + (boff[bi] ^ gx));
            #pragma unroll
            for (int mi = 0; mi < 2; mi++)
                #pragma unroll
                for (int bi = 0; bi < 4; bi++) {
                    mma8(acc[mi][2 * bi + 0], a[mi], b[bi][0], b[bi][2]);
                    mma8(acc[mi][2 * bi + 1], a[mi], b[bi][1], b[bi][3]);
                }
        }
    }

    // Epilogue
    const int r0 = m0 + wm * 32 + (lane >> 2);
    const int c0 = n0 + wn * 64 + (lane & 3) * 2;
    #pragma unroll
    for (int mi = 0; mi < 2; mi++)
        #pragma unroll
        for (int ni = 0; ni < 8; ni++) {
            float* p = C + (long long)(r0 + mi * 16) * N + c0 + ni * 8;
            float2 v0, v1;
            if (EPI_TF32) {
                v0.x = f2tf32f(acc[mi][ni][0] * alpha);
                v0.y = f2tf32f(acc[mi][ni][1] * alpha);
                v1.x = f2tf32f(acc[mi][ni][2] * alpha);
                v1.y = f2tf32f(acc[mi][ni][3] * alpha);
            } else {
                v0.x = acc[mi][ni][0] * alpha; v0.y = acc[mi][ni][1] * alpha;
                v1.x = acc[mi][ni][2] * alpha; v1.y = acc[mi][ni][3] * alpha;
            }
            *(float2*)p = v0;
            *(float2*)(p + 8LL * N) = v1;
        }
    #undef ISSUE_TILE
}

// ----------------------------------------------------------------------------
// Row softmax over rows of length SS=2048. Writes exact fp32 to attn (output)
// and a tf32-rounded copy to at32 (consumed by the AV GEMM).
// ----------------------------------------------------------------------------
__global__ __launch_bounds__(256) void softmax_kernel(
    float* __restrict__ attn, float* __restrict__ at32)
{
    __shared__ float red[256];
    const long long row = blockIdx.x;
    float* p = attn + row * (long long)SS;
    float* q = at32 + row * (long long)SS;
    const int tid = threadIdx.x;

    float v[8];
    float mx = -1e30f;
    #pragma unroll
    for (int i = 0; i < 8; i++) {
        v[i] = p[tid + i * 256];
        mx = fmaxf(mx, v[i]);
    }
    red[tid] = mx;
    __syncthreads();
    for (int s = 128; s > 0; s >>= 1) {
        if (tid < s) red[tid] = fmaxf(red[tid], red[tid + s]);
        __syncthreads();
    }
    mx = red[0];
    __syncthreads();

    float sum = 0.0f;
    #pragma unroll
    for (int i = 0; i < 8; i++) {
        v[i] = __expf(v[i] - mx);
        sum += v[i];
    }
    red[tid] = sum;
    __syncthreads();
    for (int s = 128; s > 0; s >>= 1) {
        if (tid < s) red[tid] += red[tid + s];
        __syncthreads();
    }
    const float inv = 1.0f / red[0];

    #pragma unroll
    for (int i = 0; i < 8; i++) {
        float r = v[i] * inv;
        p[tid + i * 256] = r;
        q[tid + i * 256] = f2tf32f(r);
    }
}

extern "C" void kernel_launch(void* const* d_in, const int* in_sizes, int n_in,
                              void* d_out, int out_size)
{
    const float* x  = (const float*)d_in[0];
    const float* Wq = (const float*)d_in[1];
    const float* Wk = (const float*)d_in[2];
    const float* Wv = (const float*)d_in[3];

    float* out  = (float*)d_out;                   // weighted_values [B,S,D]
    float* attn = out + (long long)BB * SS * DD;   // attention_weights [B,S,S]

    float *Q, *K, *VT, *Xt, *Wt, *At;
    cudaGetSymbolAddress((void**)&Q,  g_Q);
    cudaGetSymbolAddress((void**)&K,  g_K);
    cudaGetSymbolAddress((void**)&VT, g_VT);
    cudaGetSymbolAddress((void**)&Xt, g_Xt);
    cudaGetSymbolAddress((void**)&Wt, g_Wt);
    cudaGetSymbolAddress((void**)&At, g_At);

    dim3 blk(256);
    const float alpha = 1.0f / sqrtf((float)DD);

    // Pre-round x and W to tf32 (one pass each).
    {
        int n4x = BB * SS * DD / 4;
        cvt_tf32_kernel<<<(n4x + 255) / 256, blk>>>((const float4*)x, (float4*)Xt, n4x);
        int n4w = DD * DD / 4;
        cvt_tf32_kernel<<<(n4w + 255) / 256, blk>>>((const float4*)Wq, (float4*)(Wt + 0LL * DD * DD), n4w);
        cvt_tf32_kernel<<<(n4w + 255) / 256, blk>>>((const float4*)Wk, (float4*)(Wt + 1LL * DD * DD), n4w);
        cvt_tf32_kernel<<<(n4w + 255) / 256, blk>>>((const float4*)Wv, (float4*)(Wt + 2LL * DD * DD), n4w);
    }

    // Q = x @ Wq^T, K = x @ Wk^T  (epilogue rounds to tf32 for the scores GEMM)
    dim3 gq(DD / 128, (BB * SS) / 128, 1);
    gemm_tn_tf32<true><<<gq, blk>>>(Xt, Wt + 0LL * DD * DD, Q, BB * SS, DD, DD, 0, 0, 0, 1.0f);
    gemm_tn_tf32<true><<<gq, blk>>>(Xt, Wt + 1LL * DD * DD, K, BB * SS, DD, DD, 0, 0, 0, 1.0f);

    // V^T directly: VT_b[d][s] = sum_k Wv[d][k] * x_b[s][k]  (tf32 epilogue)
    dim3 gv(SS / 128, DD / 128, BB);
    gemm_tn_tf32<true><<<gv, blk>>>(Wt + 2LL * DD * DD, Xt, VT, DD, SS, DD,
                                    0, (long long)SS * DD, (long long)DD * SS, 1.0f);

    // Scores: attn_b = (Q_b @ K_b^T) * alpha  (fp32 epilogue -> softmax input)
    dim3 gs(SS / 128, SS / 128, BB);
    gemm_tn_tf32<false><<<gs, blk>>>(Q, K, attn, SS, SS, DD,
                                     (long long)SS * DD, (long long)SS * DD,
                                     (long long)SS * SS, alpha);

    // Softmax rows: exact fp32 -> attn (output), tf32 copy -> At
    softmax_kernel<<<BB * SS, blk>>>(attn, At);

    // Weighted values: out_b[s][d] = sum_k At_b[s][k] * VT_b[d][k]
    dim3 ga(DD / 128, SS / 128, BB);
    gemm_tn_tf32<false><<<ga, blk>>>(At, VT, out, SS, DD, SS,
                                     (long long)SS * SS, (long long)DD * SS,
                                     (long long)SS * DD, 1.0f);
}

// round 6
// speedup vs baseline: 3.8634x; 1.0057x over previous
#include <cuda_runtime.h>
#include <math.h>
#include <stdint.h>

#define BB 8
#define SS 2048
#define DD 768

// Scratch (allocation-free __device__ globals). All values tf32-rounded fp32.
__device__ float g_QK[BB * SS * (2 * DD)];  // Q|K interleaved: [B*S, 1536]
__device__ float g_VT[BB * DD * SS];        // V transposed per batch: [B][D][S]
__device__ float g_Xt[BB * SS * DD];        // x pre-rounded to tf32
__device__ float g_Wt[3 * DD * DD];         // Wq|Wk|Wv pre-rounded to tf32
__device__ float g_At[BB * SS * SS];        // softmax output rounded to tf32

__device__ __forceinline__ uint32_t f2tf32(float f) {
    uint32_t r;
    asm("cvt.rna.tf32.f32 %0, %1;" : "=r"(r) : "f"(f));
    return r;
}
__device__ __forceinline__ float f2tf32f(float f) {
    return __uint_as_float(f2tf32(f));
}
__device__ __forceinline__ uint32_t swz(uint32_t byte) {
    return byte ^ ((byte >> 3) & 0x70);
}
__device__ __forceinline__ void ldsm4(uint32_t& r0, uint32_t& r1,
                                      uint32_t& r2, uint32_t& r3, uint32_t addr) {
    asm volatile("ldmatrix.sync.aligned.m8n8.x4.shared.b16 {%0,%1,%2,%3}, [%4];"
                 : "=r"(r0), "=r"(r1), "=r"(r2), "=r"(r3) : "r"(addr));
}
__device__ __forceinline__ void mma8(float* c, const uint32_t* a,
                                     uint32_t b0, uint32_t b1) {
    asm volatile(
        "mma.sync.aligned.m16n8k8.row.col.f32.tf32.tf32.f32 "
        "{%0,%1,%2,%3}, {%4,%5,%6,%7}, {%8,%9}, {%0,%1,%2,%3};"
        : "+f"(c[0]), "+f"(c[1]), "+f"(c[2]), "+f"(c[3])
        : "r"(a[0]), "r"(a[1]), "r"(a[2]), "r"(a[3]), "r"(b0), "r"(b1));
}
__device__ __forceinline__ void cp16(uint32_t dst, const float* src) {
    asm volatile("cp.async.cg.shared.global [%0], [%1], 16;" :: "r"(dst), "l"(src));
}
__device__ __forceinline__ void cp_commit() {
    asm volatile("cp.async.commit_group;" ::: "memory");
}
__device__ __forceinline__ void cp_wait1() {
    asm volatile("cp.async.wait_group 1;" ::: "memory");
}

// ---------------------------------------------------------------------------
// Elementwise tf32 rounding.
// ---------------------------------------------------------------------------
__global__ __launch_bounds__(256) void cvt_tf32_kernel(
    const float4* __restrict__ in, float4* __restrict__ out, int n4)
{
    int i = blockIdx.x * 256 + threadIdx.x;
    if (i < n4) {
        float4 v = in[i];
        v.x = f2tf32f(v.x); v.y = f2tf32f(v.y);
        v.z = f2tf32f(v.z); v.w = f2tf32f(v.w);
        out[i] = v;
    }
}

// ---------------------------------------------------------------------------
// TN tf32 tensor-core GEMM:  C[m,n] = alpha * sum_k A[m,k]*B[n,k]
// A: MxK row-major pitch lda, B: NxK row-major pitch ldb (tf32-valued fp32).
// C row-major pitch N. Batched via blockIdx.z (element strides sA/sB/sC).
// Block tile 128x128, K-chunks of 32 (128B SW128 rows), 3-stage cp.async
// pipeline, 8 warps (4m x 2n), warp tile 32x64 of m16n8k8 tf32 MMAs.
// Requires M%128==0, N%128==0, K%32==0.
// ---------------------------------------------------------------------------
#define CK 32
#define STG_BYTES 32768            // A 16KB + B 16KB
#define DYN_SMEM  (3 * STG_BYTES)  // 98304; 2 CTAs/SM -> 192KB < 228KB

template <bool EPI_TF32>
__global__ __launch_bounds__(256, 2) void gemm_tn_tf32(
    const float* __restrict__ A, const float* __restrict__ B,
    float* __restrict__ C, int M, int N, int K, int lda, int ldb,
    long long sA, long long sB, long long sC, float alpha)
{
    extern __shared__ __align__(1024) uint8_t dynsm[];

    const int tid  = threadIdx.x;
    const int lane = tid & 31;
    const int warp = tid >> 5;
    const int wm   = warp >> 1;    // 0..3 (m, 32 rows each)
    const int wn   = warp & 1;     // 0..1 (n, 64 cols each)
    const int m0   = blockIdx.y * 128;
    const int n0   = blockIdx.x * 128;

    A += (long long)blockIdx.z * sA;
    B += (long long)blockIdx.z * sB;
    C += (long long)blockIdx.z * sC;

    const uint32_t smbase = (uint32_t)__cvta_generic_to_shared(dynsm);

    // Fill coords: 128B rows, 16B granules; A: 1024 granules (4/thr), B same.
    const int r0  = tid >> 3;            // 0..31
    const int gg  = tid & 7;             // 16B group in 128B row
    const uint32_t g16 = (uint32_t)gg * 16;
    const int g4  = gg * 4;

    const float* pa[4]; uint32_t oa[4];
    const float* pb[4]; uint32_t ob[4];
    #pragma unroll
    for (int j = 0; j < 4; j++) {
        int row = r0 + 32 * j;
        pa[j] = A + (long long)(m0 + row) * lda + g4;
        oa[j] = swz((uint32_t)row * 128 + g16);
        pb[j] = B + (long long)(n0 + row) * ldb + g4;
        ob[j] = swz((uint32_t)row * 128 + g16) + 16384;
    }

    const int KT = K / CK;

    #define FILL(t) do {                                          \
        uint32_t sb = smbase + ((t) % 3) * STG_BYTES;             \
        int ko = (t) * CK;                                        \
        _Pragma("unroll")                                         \
        for (int j = 0; j < 4; j++) {                             \
            cp16(sb + oa[j], pa[j] + ko);                         \
            cp16(sb + ob[j], pb[j] + ko);                         \
        }                                                         \
    } while (0)

    FILL(0); cp_commit();
    FILL(1); cp_commit();

    float acc[2][8][4] = {};

    // Hoisted swizzled ldsm base offsets.
    const int lrow = (lane & 7) + ((lane >> 3) & 1) * 8;
    const uint32_t glo = (uint32_t)(lane >> 4) * 16;   // 0 or 16
    uint32_t aoff[2], boff[4];
    #pragma unroll
    for (int mi = 0; mi < 2; mi++)
        aoff[mi] = swz((uint32_t)((wm * 32 + mi * 16 + lrow) * 128)) ^ glo;
    #pragma unroll
    for (int bi = 0; bi < 4; bi++)
        boff[bi] = (swz((uint32_t)((wn * 64 + bi * 16 + lrow) * 128)) ^ glo) + 16384;

    for (int i = 0; i < KT; i++) {
        cp_wait1();
        __syncthreads();
        if (i + 2 < KT) FILL(i + 2);
        cp_commit();

        const uint32_t stage = smbase + (i % 3) * STG_BYTES;

        #pragma unroll
        for (int ks = 0; ks < 4; ks++) {
            const uint32_t gx = (uint32_t)(ks * 32);   // bits 5-6, disjoint from glo
            uint32_t a[2][4], b[4][4];
            #pragma unroll
            for (int mi = 0; mi < 2; mi++)
                ldsm4(a[mi][0], a[mi][1], a[mi][2], a[mi][3],
                      stage + (aoff[mi] ^ gx));
            #pragma unroll
            for (int bi = 0; bi < 4; bi++)
                ldsm4(b[bi][0], b[bi][1], b[bi][2], b[bi][3],
                      stage + (boff[bi] ^ gx));
            #pragma unroll
            for (int mi = 0; mi < 2; mi++)
                #pragma unroll
                for (int bi = 0; bi < 4; bi++) {
                    mma8(acc[mi][2 * bi + 0], a[mi], b[bi][0], b[bi][2]);
                    mma8(acc[mi][2 * bi + 1], a[mi], b[bi][1], b[bi][3]);
                }
        }
        __syncthreads();
    }
    #undef FILL

    // Epilogue
    const int rr0 = m0 + wm * 32 + (lane >> 2);
    const int cc0 = n0 + wn * 64 + (lane & 3) * 2;
    #pragma unroll
    for (int mi = 0; mi < 2; mi++)
        #pragma unroll
        for (int ni = 0; ni < 8; ni++) {
            float* p = C + (long long)(rr0 + mi * 16) * N + cc0 + ni * 8;
            float2 v0, v1;
            if (EPI_TF32) {
                v0.x = f2tf32f(acc[mi][ni][0] * alpha);
                v0.y = f2tf32f(acc[mi][ni][1] * alpha);
                v1.x = f2tf32f(acc[mi][ni][2] * alpha);
                v1.y = f2tf32f(acc[mi][ni][3] * alpha);
            } else {
                v0.x = acc[mi][ni][0] * alpha; v0.y = acc[mi][ni][1] * alpha;
                v1.x = acc[mi][ni][2] * alpha; v1.y = acc[mi][ni][3] * alpha;
            }
            *(float2*)p = v0;
            *(float2*)(p + 8LL * N) = v1;
        }
}

// ---------------------------------------------------------------------------
// Row softmax (len 2048), shuffle reductions. Exact fp32 -> attn (output),
// tf32-rounded copy -> at32 (consumed by AV GEMM).
// ---------------------------------------------------------------------------
__global__ __launch_bounds__(256) void softmax_kernel(
    float* __restrict__ attn, float* __restrict__ at32)
{
    __shared__ float sm_max[8], sm_sum[8];
    const long long row = blockIdx.x;
    float* p = attn + row * (long long)SS;
    float* q = at32 + row * (long long)SS;
    const int tid  = threadIdx.x;
    const int lane = tid & 31;
    const int warp = tid >> 5;

    float v[8];
    float mx = -1e30f;
    #pragma unroll
    for (int i = 0; i < 8; i++) {
        v[i] = p[tid + i * 256];
        mx = fmaxf(mx, v[i]);
    }
    #pragma unroll
    for (int o = 16; o > 0; o >>= 1)
        mx = fmaxf(mx, __shfl_xor_sync(0xFFFFFFFFu, mx, o));
    if (lane == 0) sm_max[warp] = mx;
    __syncthreads();
    mx = sm_max[0];
    #pragma unroll
    for (int w = 1; w < 8; w++) mx = fmaxf(mx, sm_max[w]);

    float sum = 0.0f;
    #pragma unroll
    for (int i = 0; i < 8; i++) {
        v[i] = __expf(v[i] - mx);
        sum += v[i];
    }
    #pragma unroll
    for (int o = 16; o > 0; o >>= 1)
        sum += __shfl_xor_sync(0xFFFFFFFFu, sum, o);
    if (lane == 0) sm_sum[warp] = sum;
    __syncthreads();
    sum = 0.0f;
    #pragma unroll
    for (int w = 0; w < 8; w++) sum += sm_sum[w];
    const float inv = 1.0f / sum;

    #pragma unroll
    for (int i = 0; i < 8; i++) {
        float r = v[i] * inv;
        p[tid + i * 256] = r;
        q[tid + i * 256] = f2tf32f(r);
    }
}

extern "C" void kernel_launch(void* const* d_in, const int* in_sizes, int n_in,
                              void* d_out, int out_size)
{
    const float* x  = (const float*)d_in[0];
    const float* Wq = (const float*)d_in[1];
    const float* Wk = (const float*)d_in[2];
    const float* Wv = (const float*)d_in[3];

    float* out  = (float*)d_out;                   // weighted_values [B,S,D]
    float* attn = out + (long long)BB * SS * DD;   // attention_weights [B,S,S]

    float *QK, *VT, *Xt, *Wt, *At;
    cudaGetSymbolAddress((void**)&QK, g_QK);
    cudaGetSymbolAddress((void**)&VT, g_VT);
    cudaGetSymbolAddress((void**)&Xt, g_Xt);
    cudaGetSymbolAddress((void**)&Wt, g_Wt);
    cudaGetSymbolAddress((void**)&At, g_At);

    cudaFuncSetAttribute(gemm_tn_tf32<true>,
                         cudaFuncAttributeMaxDynamicSharedMemorySize, DYN_SMEM);
    cudaFuncSetAttribute(gemm_tn_tf32<false>,
                         cudaFuncAttributeMaxDynamicSharedMemorySize, DYN_SMEM);

    dim3 blk(256);
    const float alpha = 1.0f / sqrtf((float)DD);

    // Pre-round x and W to tf32. Wq|Wk|Wv land contiguously in Wt.
    {
        int n4x = BB * SS * DD / 4;
        cvt_tf32_kernel<<<(n4x + 255) / 256, blk>>>((const float4*)x, (float4*)Xt, n4x);
        int n4w = DD * DD / 4;
        cvt_tf32_kernel<<<(n4w + 255) / 256, blk>>>((const float4*)Wq, (float4*)(Wt + 0LL * DD * DD), n4w);
        cvt_tf32_kernel<<<(n4w + 255) / 256, blk>>>((const float4*)Wk, (float4*)(Wt + 1LL * DD * DD), n4w);
        cvt_tf32_kernel<<<(n4w + 255) / 256, blk>>>((const float4*)Wv, (float4*)(Wt + 2LL * DD * DD), n4w);
    }

    // Fused Q|K projection: QK[m, 0:768]=Q, QK[m, 768:1536]=K.
    // B = Wt (rows 0..1535 = Wq|Wk), N=1536. tf32 epilogue.
    dim3 gqk((2 * DD) / 128, (BB * SS) / 128, 1);
    gemm_tn_tf32<true><<<gqk, blk, DYN_SMEM>>>(Xt, Wt, QK,
        BB * SS, 2 * DD, DD, DD, DD, 0, 0, 0, 1.0f);

    // V^T: VT_b[d][s] = sum_k Wv[d][k] * x_b[s][k]. tf32 epilogue.
    dim3 gv(SS / 128, DD / 128, BB);
    gemm_tn_tf32<true><<<gv, blk, DYN_SMEM>>>(Wt + 2LL * DD * DD, Xt, VT,
        DD, SS, DD, DD, DD, 0, (long long)SS * DD, (long long)DD * SS, 1.0f);

    // Scores: attn_b = (Q_b @ K_b^T) * alpha. Q/K strided out of QK (pitch 1536).
    dim3 gs(SS / 128, SS / 128, BB);
    gemm_tn_tf32<false><<<gs, blk, DYN_SMEM>>>(QK, QK + DD, attn,
        SS, SS, DD, 2 * DD, 2 * DD,
        (long long)SS * 2 * DD, (long long)SS * 2 * DD, (long long)SS * SS, alpha);

    // Softmax rows: exact fp32 -> attn, tf32 -> At.
    softmax_kernel<<<BB * SS, blk>>>(attn, At);

    // Weighted values: out_b[s][d] = sum_k At_b[s][k] * VT_b[d][k].
    dim3 ga(DD / 128, SS / 128, BB);
    gemm_tn_tf32<false><<<ga, blk, DYN_SMEM>>>(At, VT, out,
        SS, DD, SS, SS, SS,
        (long long)SS * SS, (long long)DD * SS, (long long)SS * DD, 1.0f);
}

// round 7
// speedup vs baseline: 6.8904x; 1.7835x over previous
#include <cuda_runtime.h>
#include <cuda_fp16.h>
#include <math.h>
#include <stdint.h>

#define BB 8
#define SS 2048
#define DD 768

// Scratch (allocation-free __device__ globals). fp16 operands everywhere.
__device__ __half g_QK[BB * SS * (2 * DD)];  // Q|K interleaved: [B*S, 1536]
__device__ __half g_VT[BB * DD * SS];        // V transposed per batch: [B][D][S]
__device__ __half g_Xh[BB * SS * DD];        // x in fp16
__device__ __half g_Wh[3 * DD * DD];         // Wq|Wk|Wv in fp16
__device__ __half g_At[BB * SS * SS];        // softmax output in fp16

__device__ __forceinline__ uint32_t swz(uint32_t byte) {
    return byte ^ ((byte >> 3) & 0x70);
}
__device__ __forceinline__ void ldsm4(uint32_t& r0, uint32_t& r1,
                                      uint32_t& r2, uint32_t& r3, uint32_t addr) {
    asm volatile("ldmatrix.sync.aligned.m8n8.x4.shared.b16 {%0,%1,%2,%3}, [%4];"
                 : "=r"(r0), "=r"(r1), "=r"(r2), "=r"(r3) : "r"(addr));
}
__device__ __forceinline__ void mma16(float* c, const uint32_t* a,
                                      uint32_t b0, uint32_t b1) {
    asm volatile(
        "mma.sync.aligned.m16n8k16.row.col.f32.f16.f16.f32 "
        "{%0,%1,%2,%3}, {%4,%5,%6,%7}, {%8,%9}, {%0,%1,%2,%3};"
        : "+f"(c[0]), "+f"(c[1]), "+f"(c[2]), "+f"(c[3])
        : "r"(a[0]), "r"(a[1]), "r"(a[2]), "r"(a[3]), "r"(b0), "r"(b1));
}
__device__ __forceinline__ void cp16(uint32_t dst, const void* src) {
    asm volatile("cp.async.cg.shared.global [%0], [%1], 16;" :: "r"(dst), "l"(src));
}
__device__ __forceinline__ void cp_commit() {
    asm volatile("cp.async.commit_group;" ::: "memory");
}
__device__ __forceinline__ void cp_wait1() {
    asm volatile("cp.async.wait_group 1;" ::: "memory");
}

// ---------------------------------------------------------------------------
// Elementwise fp32 -> fp16.
// ---------------------------------------------------------------------------
__global__ __launch_bounds__(256) void cvt_f16_kernel(
    const float4* __restrict__ in, uint2* __restrict__ out, int n4)
{
    int i = blockIdx.x * 256 + threadIdx.x;
    if (i < n4) {
        float4 v = in[i];
        __half2 h01 = __floats2half2_rn(v.x, v.y);
        __half2 h23 = __floats2half2_rn(v.z, v.w);
        uint2 u;
        u.x = *reinterpret_cast<uint32_t*>(&h01);
        u.y = *reinterpret_cast<uint32_t*>(&h23);
        out[i] = u;
    }
}

// ---------------------------------------------------------------------------
// TN fp16 tensor-core GEMM:  C[m,n] = alpha * sum_k A[m,k]*B[n,k]
// A: MxK fp16 row-major pitch lda, B: NxK fp16 row-major pitch ldb.
// OUT=0: C fp32 (pitch N); OUT=1: C fp16 (pitch N).
// Batched via blockIdx.z (element strides). Block tile 128x128, K-chunks of
// 64 (128B SW128 rows), 3-stage cp.async, 8 warps (4m x 2n), warp tile 32x64
// of m16n8k16 MMAs. Requires M%128==0, N%128==0, K%64==0.
// ---------------------------------------------------------------------------
#define CK 64
#define STG_BYTES 32768            // A 16KB + B 16KB
#define DYN_SMEM  (3 * STG_BYTES)  // 98304; 2 CTAs/SM

template <int OUT>
__global__ __launch_bounds__(256, 2) void gemm_tn_f16(
    const __half* __restrict__ A, const __half* __restrict__ B,
    void* __restrict__ Cv, int M, int N, int K, int lda, int ldb,
    long long sA, long long sB, long long sC, float alpha)
{
    extern __shared__ __align__(1024) uint8_t dynsm[];

    const int tid  = threadIdx.x;
    const int lane = tid & 31;
    const int warp = tid >> 5;
    const int wm   = warp >> 1;    // 0..3 (m, 32 rows each)
    const int wn   = warp & 1;     // 0..1 (n, 64 cols each)
    const int m0   = blockIdx.y * 128;
    const int n0   = blockIdx.x * 128;

    A += (long long)blockIdx.z * sA;
    B += (long long)blockIdx.z * sB;

    const uint32_t smbase = (uint32_t)__cvta_generic_to_shared(dynsm);

    // Fill coords: 128B rows (64 halves), 16B granules (8 halves).
    // Per chunk: A 1024 granules (4/thr), B same.
    const int r0  = tid >> 3;            // 0..31
    const int gg  = tid & 7;             // granule in row
    const uint32_t g16 = (uint32_t)gg * 16;

    const __half* pa[4]; uint32_t oa[4];
    const __half* pb[4]; uint32_t ob[4];
    #pragma unroll
    for (int j = 0; j < 4; j++) {
        int row = r0 + 32 * j;
        pa[j] = A + (long long)(m0 + row) * lda + gg * 8;
        oa[j] = swz((uint32_t)row * 128 + g16);
        pb[j] = B + (long long)(n0 + row) * ldb + gg * 8;
        ob[j] = swz((uint32_t)row * 128 + g16) + 16384;
    }

    const int KT = K / CK;

    #define FILL(t) do {                                          \
        uint32_t sb = smbase + ((t) % 3) * STG_BYTES;             \
        int ko = (t) * CK;                                        \
        _Pragma("unroll")                                         \
        for (int j = 0; j < 4; j++) {                             \
            cp16(sb + oa[j], pa[j] + ko);                         \
            cp16(sb + ob[j], pb[j] + ko);                         \
        }                                                         \
    } while (0)

    FILL(0); cp_commit();
    FILL(1); cp_commit();

    float acc[2][8][4] = {};

    // Hoisted swizzled ldsm base offsets.
    // lanes 0-7: rows 0-7 (+0B), 8-15: rows 8-15 (+0B),
    // 16-23: rows 0-7 (+16B = k8-15), 24-31: rows 8-15 (+16B).
    const int lrow = (lane & 7) + ((lane >> 3) & 1) * 8;
    const uint32_t glo = (uint32_t)(lane >> 4) * 16;
    uint32_t aoff[2], boff[4];
    #pragma unroll
    for (int mi = 0; mi < 2; mi++)
        aoff[mi] = swz((uint32_t)((wm * 32 + mi * 16 + lrow) * 128)) ^ glo;
    #pragma unroll
    for (int l = 0; l < 4; l++)
        boff[l] = (swz((uint32_t)((wn * 64 + l * 16 + lrow) * 128)) ^ glo) + 16384;

    for (int i = 0; i < KT; i++) {
        cp_wait1();
        __syncthreads();
        if (i + 2 < KT) FILL(i + 2);
        cp_commit();

        const uint32_t stage = smbase + (i % 3) * STG_BYTES;

        #pragma unroll
        for (int ks = 0; ks < 4; ks++) {            // k16 steps within k64
            const uint32_t gx = (uint32_t)(ks * 32); // bits 5-6, disjoint from glo
            uint32_t a[2][4], b[4][4];
            #pragma unroll
            for (int mi = 0; mi < 2; mi++)
                ldsm4(a[mi][0], a[mi][1], a[mi][2], a[mi][3],
                      stage + (aoff[mi] ^ gx));
            #pragma unroll
            for (int l = 0; l < 4; l++)
                ldsm4(b[l][0], b[l][1], b[l][2], b[l][3],
                      stage + (boff[l] ^ gx));
            #pragma unroll
            for (int mi = 0; mi < 2; mi++)
                #pragma unroll
                for (int j = 0; j < 8; j++) {
                    const int l = j >> 1, o = j & 1;
                    mma16(acc[mi][j], a[mi], b[l][o], b[l][o + 2]);
                }
        }
        __syncthreads();
    }
    #undef FILL

    // Epilogue (m16n8 accumulator layout: rows r, r+8; col pairs).
    const int rr0 = m0 + wm * 32 + (lane >> 2);
    const int cc0 = n0 + wn * 64 + (lane & 3) * 2;
    if (OUT == 0) {
        float* C = (float*)Cv + (long long)blockIdx.z * sC;
        #pragma unroll
        for (int mi = 0; mi < 2; mi++)
            #pragma unroll
            for (int ni = 0; ni < 8; ni++) {
                float* p = C + (long long)(rr0 + mi * 16) * N + cc0 + ni * 8;
                float2 v0, v1;
                v0.x = acc[mi][ni][0] * alpha; v0.y = acc[mi][ni][1] * alpha;
                v1.x = acc[mi][ni][2] * alpha; v1.y = acc[mi][ni][3] * alpha;
                *(float2*)p = v0;
                *(float2*)(p + 8LL * N) = v1;
            }
    } else {
        __half* C = (__half*)Cv + (long long)blockIdx.z * sC;
        #pragma unroll
        for (int mi = 0; mi < 2; mi++)
            #pragma unroll
            for (int ni = 0; ni < 8; ni++) {
                __half* p = C + (long long)(rr0 + mi * 16) * N + cc0 + ni * 8;
                *(__half2*)p =
                    __floats2half2_rn(acc[mi][ni][0] * alpha, acc[mi][ni][1] * alpha);
                *(__half2*)(p + 8LL * N) =
                    __floats2half2_rn(acc[mi][ni][2] * alpha, acc[mi][ni][3] * alpha);
            }
    }
}

// ---------------------------------------------------------------------------
// Row softmax (len 2048), shuffle reductions. Exact fp32 -> attn (output),
// fp16 copy -> at16 (consumed by AV GEMM).
// ---------------------------------------------------------------------------
__global__ __launch_bounds__(256) void softmax_kernel(
    float* __restrict__ attn, __half* __restrict__ at16)
{
    __shared__ float sm_max[8], sm_sum[8];
    const long long row = blockIdx.x;
    float2*  p2 = (float2*)(attn + row * (long long)SS);
    __half2* q2 = (__half2*)(at16 + row * (long long)SS);
    const int tid  = threadIdx.x;
    const int lane = tid & 31;
    const int warp = tid >> 5;

    float2 v[4];
    float mx = -1e30f;
    #pragma unroll
    for (int i = 0; i < 4; i++) {
        v[i] = p2[tid + i * 256];
        mx = fmaxf(mx, fmaxf(v[i].x, v[i].y));
    }
    #pragma unroll
    for (int o = 16; o > 0; o >>= 1)
        mx = fmaxf(mx, __shfl_xor_sync(0xFFFFFFFFu, mx, o));
    if (lane == 0) sm_max[warp] = mx;
    __syncthreads();
    mx = sm_max[0];
    #pragma unroll
    for (int w = 1; w < 8; w++) mx = fmaxf(mx, sm_max[w]);

    float sum = 0.0f;
    #pragma unroll
    for (int i = 0; i < 4; i++) {
        v[i].x = __expf(v[i].x - mx);
        v[i].y = __expf(v[i].y - mx);
        sum += v[i].x + v[i].y;
    }
    #pragma unroll
    for (int o = 16; o > 0; o >>= 1)
        sum += __shfl_xor_sync(0xFFFFFFFFu, sum, o);
    if (lane == 0) sm_sum[warp] = sum;
    __syncthreads();
    sum = 0.0f;
    #pragma unroll
    for (int w = 0; w < 8; w++) sum += sm_sum[w];
    const float inv = 1.0f / sum;

    #pragma unroll
    for (int i = 0; i < 4; i++) {
        float r0 = v[i].x * inv, r1 = v[i].y * inv;
        p2[tid + i * 256] = make_float2(r0, r1);
        q2[tid + i * 256] = __floats2half2_rn(r0, r1);
    }
}

extern "C" void kernel_launch(void* const* d_in, const int* in_sizes, int n_in,
                              void* d_out, int out_size)
{
    const float* x  = (const float*)d_in[0];
    const float* Wq = (const float*)d_in[1];
    const float* Wk = (const float*)d_in[2];
    const float* Wv = (const float*)d_in[3];

    float* out  = (float*)d_out;                   // weighted_values [B,S,D]
    float* attn = out + (long long)BB * SS * DD;   // attention_weights [B,S,S]

    __half *QK, *VT, *Xh, *Wh, *At;
    cudaGetSymbolAddress((void**)&QK, g_QK);
    cudaGetSymbolAddress((void**)&VT, g_VT);
    cudaGetSymbolAddress((void**)&Xh, g_Xh);
    cudaGetSymbolAddress((void**)&Wh, g_Wh);
    cudaGetSymbolAddress((void**)&At, g_At);

    cudaFuncSetAttribute(gemm_tn_f16<0>,
                         cudaFuncAttributeMaxDynamicSharedMemorySize, DYN_SMEM);
    cudaFuncSetAttribute(gemm_tn_f16<1>,
                         cudaFuncAttributeMaxDynamicSharedMemorySize, DYN_SMEM);

    dim3 blk(256);
    const float alpha = 1.0f / sqrtf((float)DD);

    // fp32 -> fp16 operand conversion. Wq|Wk|Wv land contiguously in Wh.
    {
        int n4x = BB * SS * DD / 4;
        cvt_f16_kernel<<<(n4x + 255) / 256, blk>>>((const float4*)x, (uint2*)Xh, n4x);
        int n4w = DD * DD / 4;
        cvt_f16_kernel<<<(n4w + 255) / 256, blk>>>((const float4*)Wq, (uint2*)(Wh + 0LL * DD * DD), n4w);
        cvt_f16_kernel<<<(n4w + 255) / 256, blk>>>((const float4*)Wk, (uint2*)(Wh + 1LL * DD * DD), n4w);
        cvt_f16_kernel<<<(n4w + 255) / 256, blk>>>((const float4*)Wv, (uint2*)(Wh + 2LL * DD * DD), n4w);
    }

    // Fused Q|K projection: QK[m, 0:768]=Q, QK[m, 768:1536]=K (fp16 out).
    dim3 gqk((2 * DD) / 128, (BB * SS) / 128, 1);
    gemm_tn_f16<1><<<gqk, blk, DYN_SMEM>>>(Xh, Wh, QK,
        BB * SS, 2 * DD, DD, DD, DD, 0, 0, 0, 1.0f);

    // V^T: VT_b[d][s] = sum_k Wv[d][k] * x_b[s][k] (fp16 out).
    dim3 gv(SS / 128, DD / 128, BB);
    gemm_tn_f16<1><<<gv, blk, DYN_SMEM>>>(Wh + 2LL * DD * DD, Xh, VT,
        DD, SS, DD, DD, DD, 0, (long long)SS * DD, (long long)DD * SS, 1.0f);

    // Scores: attn_b = (Q_b @ K_b^T) * alpha (fp32 out).
    dim3 gs(SS / 128, SS / 128, BB);
    gemm_tn_f16<0><<<gs, blk, DYN_SMEM>>>(QK, QK + DD, attn,
        SS, SS, DD, 2 * DD, 2 * DD,
        (long long)SS * 2 * DD, (long long)SS * 2 * DD, (long long)SS * SS, alpha);

    // Softmax rows: exact fp32 -> attn, fp16 -> At.
    softmax_kernel<<<BB * SS, blk>>>(attn, At);

    // Weighted values: out_b[s][d] = sum_k At_b[s][k] * VT_b[d][k] (fp32 out).
    dim3 ga(DD / 128, SS / 128, BB);
    gemm_tn_f16<0><<<ga, blk, DYN_SMEM>>>(At, VT, out,
        SS, DD, SS, SS, SS,
        (long long)SS * SS, (long long)DD * SS, (long long)SS * DD, 1.0f);
}